// round 5
// baseline (speedup 1.0000x reference)
#include <cuda_runtime.h>
#include <cstdint>

#define N_NODES 100000
#define N_EDGES 1250000
#define DFEAT   64
#define UNITS   64

#define NBLOCKS 148
#define NT      512
#define TOTALT  (NBLOCKS * NT)
#define CH      ((N_NODES + NBLOCKS - 1) / NBLOCKS)   // 676 nodes per block for scan
#define E4      (N_EDGES / 4)                          // 312500

// ---- scratch (device globals; allocation-free) ----
__device__ float4 g_U[(size_t)N_NODES * (UNITS / 4)];  // dinv[n]*(F[n]@W), 25.6 MB
__device__ int    g_degi[N_NODES];
__device__ float  g_dinv[N_NODES];
__device__ int    g_scan[N_NODES];                     // block-local exclusive scan
__device__ int    g_bsum[NBLOCKS];
__device__ int    g_boff[NBLOCKS];
__device__ int    g_rowptr[N_NODES + 1];
__device__ int    g_fill[N_NODES];
__device__ int    g_col[N_EDGES];
__device__ int    g_is64;

// ---- grid-wide barrier (monotonic generation; state self-restoring) ----
__device__ unsigned g_bar_count = 0;
__device__ unsigned g_bar_gen   = 0;

__device__ __forceinline__ void grid_barrier() {
    __syncthreads();
    if (threadIdx.x == 0) {
        __threadfence();
        unsigned gen = atomicAdd(&g_bar_gen, 0u);          // current generation
        unsigned old = atomicAdd(&g_bar_count, 1u);
        if (old == NBLOCKS - 1) {
            atomicExch(&g_bar_count, 0u);
            __threadfence();
            atomicAdd(&g_bar_gen, 1u);
        } else {
            while (atomicAdd(&g_bar_gen, 0u) == gen) __nanosleep(64);
            __threadfence();
        }
    }
    __syncthreads();
}

// f32x2 packed FMA helpers (Blackwell FFMA2)
#define FMA_F32X2(acc, a, b) \
    asm("fma.rn.f32x2 %0, %1, %2, %0;" : "+l"(acc) : "l"(a), "l"(b))
#define PACK_DUP_F32X2(out, s) \
    asm("mov.b64 %0, {%1, %1};" : "=l"(out) : "r"(s))

__device__ __forceinline__ void load_edges4(const void* __restrict__ ei,
                                            int t, size_t elem_off, int v[4], int is64) {
    if (is64) {
        const longlong2* p = (const longlong2*)((const long long*)ei + elem_off);
        longlong2 a = p[t * 2];
        longlong2 b = p[t * 2 + 1];
        v[0] = (int)a.x; v[1] = (int)a.y; v[2] = (int)b.x; v[3] = (int)b.y;
    } else {
        int4 a = ((const int4*)((const int*)ei + elem_off))[t];
        v[0] = a.x; v[1] = a.y; v[2] = a.z; v[3] = a.w;
    }
}

// ---------------------------------------------------------------------------
// THE kernel: whole pipeline, one launch, 7 phases / 6 grid barriers
// ---------------------------------------------------------------------------
__global__ void __launch_bounds__(NT, 1)
k_fused(const float* __restrict__ F, const void* __restrict__ ei,
        const float* __restrict__ W, const float* __restrict__ bias,
        float4* __restrict__ out4) {
    __shared__ __align__(16) unsigned char s_raw[16384];   // reused per phase
    float4* Ws     = (float4*)s_raw;                       // transform: 16 KB
    int*    s_scan = (int*)s_raw;                          // scans: <= 2 KB

    const int tid  = threadIdx.x;
    const int bid  = blockIdx.x;
    const int gtid = bid * NT + tid;

    // ---- P0: zero degree counters + dtype detect ----
    for (int i = gtid; i < N_NODES; i += TOTALT) g_degi[i] = 0;
    if (bid == 0 && tid < 32) {
        const long long* p = (const long long*)ei;
        int bad = 0;
#pragma unroll
        for (int k = 0; k < 8; k++) {
            long long v = p[tid * 8 + k];
            bad |= (v < 0 || v >= N_NODES);
        }
        unsigned any = __ballot_sync(0xFFFFFFFFu, bad);
        if (tid == 0) g_is64 = (any == 0u) ? 1 : 0;
    }
    grid_barrier();

    const int is64 = g_is64;

    // ---- P1: degree count (4 edges/thread, vector loads) ----
    for (int t = gtid; t < E4; t += TOTALT) {
        int r[4];
        load_edges4(ei, t, 0, r, is64);
#pragma unroll
        for (int k = 0; k < 4; k++) atomicAdd(&g_degi[r[k]], 1);
    }
    grid_barrier();

    // ---- P2: block-local scan over this block's node chunk (2 nodes/thread) ----
    {
        int base = bid * CH;
        int lim  = min(N_NODES, base + CH);
        int i0 = base + tid * 2;
        int d0 = (i0     < lim) ? g_degi[i0]     : 0;
        int d1 = (i0 + 1 < lim) ? g_degi[i0 + 1] : 0;
        int sum = d0 + d1;
        s_scan[tid] = sum;
        __syncthreads();
#pragma unroll
        for (int off = 1; off < NT; off <<= 1) {
            int t = (tid >= off) ? s_scan[tid - off] : 0;
            __syncthreads();
            s_scan[tid] += t;
            __syncthreads();
        }
        int incl = s_scan[tid];
        int excl = incl - sum;
        if (i0     < lim) g_scan[i0]     = excl;
        if (i0 + 1 < lim) g_scan[i0 + 1] = excl + d0;
        if (tid == NT - 1) g_bsum[bid] = incl;
    }
    grid_barrier();

    // ---- P3: scan of block sums (block 0 only) ----
    if (bid == 0) {
        int v = (tid < NBLOCKS) ? g_bsum[tid] : 0;
        s_scan[tid] = v;
        __syncthreads();
#pragma unroll
        for (int off = 1; off < NT; off <<= 1) {
            int t = (tid >= off) ? s_scan[tid - off] : 0;
            __syncthreads();
            s_scan[tid] += t;
            __syncthreads();
        }
        if (tid < NBLOCKS) g_boff[tid] = s_scan[tid] - v;   // exclusive
    }
    grid_barrier();

    // ---- P4: finalize rowptr / fill / dinv ----
    for (int i = gtid; i < N_NODES; i += TOTALT) {
        int d    = g_degi[i];
        int excl = g_scan[i] + g_boff[i / CH];
        g_rowptr[i] = excl;
        g_fill[i]   = excl;
        g_dinv[i]   = (d > 0) ? rsqrtf((float)d) : 0.f;
    }
    if (gtid == 0) g_rowptr[N_NODES] = N_EDGES;
    grid_barrier();

    // ---- P5a: transform U[n] = dinv[n]*(F[n]@W)  (packed f32x2 FMA) ----
    for (int i = tid; i < DFEAT * (UNITS / 4); i += NT)
        Ws[i] = reinterpret_cast<const float4*>(W)[i];
    __syncthreads();

    for (int node = gtid; node < N_NODES; node += TOTALT) {
        unsigned long long acc[32];
#pragma unroll
        for (int j = 0; j < 32; j++) acc[j] = 0ull;
        const float4* Frow = reinterpret_cast<const float4*>(F + (size_t)node * DFEAT);
#pragma unroll 4
        for (int k4 = 0; k4 < 16; k4++) {
            float4 f = Frow[k4];
            float fv[4] = {f.x, f.y, f.z, f.w};
#pragma unroll
            for (int kk = 0; kk < 4; kk++) {
                unsigned long long p2;
                PACK_DUP_F32X2(p2, __float_as_uint(fv[kk]));
                const unsigned long long* wrow =
                    reinterpret_cast<const unsigned long long*>(&Ws[(k4 * 4 + kk) * 16]);
#pragma unroll
                for (int j = 0; j < 32; j++) FMA_F32X2(acc[j], p2, wrow[j]);
            }
        }
        float dv = g_dinv[node];
        float4* Urow = &g_U[(size_t)node * 16];
#pragma unroll
        for (int j = 0; j < 16; j++) {
            float2 lo = *reinterpret_cast<float2*>(&acc[2 * j]);
            float2 hi = *reinterpret_cast<float2*>(&acc[2 * j + 1]);
            Urow[j] = make_float4(lo.x * dv, lo.y * dv, hi.x * dv, hi.y * dv);
        }
    }

    // ---- P5b: CSR fill (same phase: overlaps with other blocks' transform) ----
    for (int t = gtid; t < E4; t += TOTALT) {
        int r[4], c[4];
        load_edges4(ei, t, 0, r, is64);
        load_edges4(ei, t, N_EDGES, c, is64);
#pragma unroll
        for (int k = 0; k < 4; k++) {
            int pos = atomicAdd(&g_fill[r[k]], 1);
            g_col[pos] = c[k];
        }
    }
    grid_barrier();

    // ---- P6: gather + epilogue (no atomics) ----
    for (int w = gtid; w < N_NODES * 16; w += TOTALT) {
        int node = w >> 4;
        int c    = w & 15;
        int start = g_rowptr[node];
        int end   = g_rowptr[node + 1];

        float4 acc0 = make_float4(0.f, 0.f, 0.f, 0.f);
        float4 acc1 = make_float4(0.f, 0.f, 0.f, 0.f);
        int j = start;
        for (; j + 3 < end; j += 4) {
            int c0 = g_col[j];
            int c1 = g_col[j + 1];
            int c2 = g_col[j + 2];
            int c3 = g_col[j + 3];
            float4 a = g_U[c0 * 16 + c];
            float4 b = g_U[c1 * 16 + c];
            float4 d = g_U[c2 * 16 + c];
            float4 e = g_U[c3 * 16 + c];
            acc0.x += a.x + b.x;  acc0.y += a.y + b.y;
            acc0.z += a.z + b.z;  acc0.w += a.w + b.w;
            acc1.x += d.x + e.x;  acc1.y += d.y + e.y;
            acc1.z += d.z + e.z;  acc1.w += d.w + e.w;
        }
        for (; j < end; j++) {
            float4 a = g_U[g_col[j] * 16 + c];
            acc0.x += a.x; acc0.y += a.y; acc0.z += a.z; acc0.w += a.w;
        }
        acc0.x += acc1.x; acc0.y += acc1.y; acc0.z += acc1.z; acc0.w += acc1.w;

        float dv = g_dinv[node];
        float4 b4 = reinterpret_cast<const float4*>(bias)[c];
        float4 v;
        v.x = fmaxf(fmaf(dv, acc0.x, b4.x), 0.f);
        v.y = fmaxf(fmaf(dv, acc0.y, b4.y), 0.f);
        v.z = fmaxf(fmaf(dv, acc0.z, b4.z), 0.f);
        v.w = fmaxf(fmaf(dv, acc0.w, b4.w), 0.f);
        out4[node * 16 + c] = v;
    }
}

// ---------------------------------------------------------------------------
extern "C" void kernel_launch(void* const* d_in, const int* in_sizes, int n_in,
                              void* d_out, int out_size) {
    const float* features = (const float*)d_in[0];       // [N, 64]
    const void*  edge_idx = d_in[1];                     // [2, E] int32 or int64
    const float* weight   = (const float*)d_in[2];       // [64, 64]
    const float* bias     = (const float*)d_in[3];       // [64]
    float4*      out4     = (float4*)d_out;              // [N, 64] fp32

    k_fused<<<NBLOCKS, NT>>>(features, edge_idx, weight, bias, out4);
}

// round 6
// speedup vs baseline: 1.0273x; 1.0273x over previous
#include <cuda_runtime.h>
#include <cstdint>

#define N_NODES 100000
#define N_EDGES 1250000
#define DFEAT   64
#define UNITS   64

#define NBLOCKS 148
#define NT      512
#define TOTALT  (NBLOCKS * NT)
#define CH      ((N_NODES + NBLOCKS - 1) / NBLOCKS)   // 676 nodes/block for scan
#define E4      (N_EDGES / 4)                          // 312500

// ---- scratch (device globals; allocation-free) ----
__device__ float4 g_U[(size_t)N_NODES * (UNITS / 4)];  // dinv[n]*(F[n]@W), 25.6 MB
__device__ int    g_degi[N_NODES];
__device__ float  g_dinv[N_NODES];
__device__ int    g_scan[N_NODES];
__device__ int    g_bsum[NBLOCKS];
__device__ int    g_boff[NBLOCKS];
__device__ int    g_rowptr[N_NODES + 1];
__device__ int    g_fill[N_NODES];
__device__ int    g_col[N_EDGES];
__device__ int    g_is64;

// ---- grid-wide barrier (monotonic generation; state self-restoring) ----
__device__ unsigned g_bar_count = 0;
__device__ unsigned g_bar_gen   = 0;

__device__ __forceinline__ void grid_barrier() {
    __syncthreads();
    if (threadIdx.x == 0) {
        __threadfence();
        unsigned gen = atomicAdd(&g_bar_gen, 0u);
        unsigned old = atomicAdd(&g_bar_count, 1u);
        if (old == NBLOCKS - 1) {
            atomicExch(&g_bar_count, 0u);
            __threadfence();
            atomicAdd(&g_bar_gen, 1u);
        } else {
            while (atomicAdd(&g_bar_gen, 0u) == gen) __nanosleep(64);
            __threadfence();
        }
    }
    __syncthreads();
}

// f32x2 packed FMA helpers (Blackwell FFMA2)
#define FMA_F32X2(acc, a, b) \
    asm("fma.rn.f32x2 %0, %1, %2, %0;" : "+l"(acc) : "l"(a), "l"(b))
#define PACK_DUP_F32X2(out, s) \
    asm("mov.b64 %0, {%1, %1};" : "=l"(out) : "r"(s))

__device__ __forceinline__ void load_edges4(const void* __restrict__ ei,
                                            int t, size_t elem_off, int v[4], int is64) {
    if (is64) {
        const longlong2* p = (const longlong2*)((const long long*)ei + elem_off);
        longlong2 a = p[t * 2];
        longlong2 b = p[t * 2 + 1];
        v[0] = (int)a.x; v[1] = (int)a.y; v[2] = (int)b.x; v[3] = (int)b.y;
    } else {
        int4 a = ((const int4*)((const int*)ei + elem_off))[t];
        v[0] = a.x; v[1] = a.y; v[2] = a.z; v[3] = a.w;
    }
}

// ---------------------------------------------------------------------------
// Kernel A: persistent setup + transform + fill (everything except gather)
// ---------------------------------------------------------------------------
__global__ void __launch_bounds__(NT, 1)
k_setup(const float* __restrict__ F, const void* __restrict__ ei,
        const float* __restrict__ W) {
    __shared__ __align__(16) unsigned char s_raw[16384];
    float4* Ws     = (float4*)s_raw;
    int*    s_scan = (int*)s_raw;

    const int tid  = threadIdx.x;
    const int bid  = blockIdx.x;
    const int gtid = bid * NT + tid;

    // ---- P0: zero degree counters + dtype detect ----
    for (int i = gtid; i < N_NODES; i += TOTALT) g_degi[i] = 0;
    if (bid == 0 && tid < 32) {
        const long long* p = (const long long*)ei;
        int bad = 0;
#pragma unroll
        for (int k = 0; k < 8; k++) {
            long long v = p[tid * 8 + k];
            bad |= (v < 0 || v >= N_NODES);
        }
        unsigned any = __ballot_sync(0xFFFFFFFFu, bad);
        if (tid == 0) g_is64 = (any == 0u) ? 1 : 0;
    }
    grid_barrier();

    const int is64 = g_is64;

    // ---- P1: degree count ----
    for (int t = gtid; t < E4; t += TOTALT) {
        int r[4];
        load_edges4(ei, t, 0, r, is64);
#pragma unroll
        for (int k = 0; k < 4; k++) atomicAdd(&g_degi[r[k]], 1);
    }
    grid_barrier();

    // ---- P2: block-local scan (2 nodes/thread) ----
    {
        int base = bid * CH;
        int lim  = min(N_NODES, base + CH);
        int i0 = base + tid * 2;
        int d0 = (i0     < lim) ? g_degi[i0]     : 0;
        int d1 = (i0 + 1 < lim) ? g_degi[i0 + 1] : 0;
        int sum = d0 + d1;
        s_scan[tid] = sum;
        __syncthreads();
#pragma unroll
        for (int off = 1; off < NT; off <<= 1) {
            int t = (tid >= off) ? s_scan[tid - off] : 0;
            __syncthreads();
            s_scan[tid] += t;
            __syncthreads();
        }
        int incl = s_scan[tid];
        int excl = incl - sum;
        if (i0     < lim) g_scan[i0]     = excl;
        if (i0 + 1 < lim) g_scan[i0 + 1] = excl + d0;
        if (tid == NT - 1) g_bsum[bid] = incl;
    }
    grid_barrier();

    // ---- P3: scan of block sums (block 0) ----
    if (bid == 0) {
        int v = (tid < NBLOCKS) ? g_bsum[tid] : 0;
        s_scan[tid] = v;
        __syncthreads();
#pragma unroll
        for (int off = 1; off < NT; off <<= 1) {
            int t = (tid >= off) ? s_scan[tid - off] : 0;
            __syncthreads();
            s_scan[tid] += t;
            __syncthreads();
        }
        if (tid < NBLOCKS) g_boff[tid] = s_scan[tid] - v;
    }
    grid_barrier();

    // ---- P4: finalize rowptr / fill / dinv ----
    for (int i = gtid; i < N_NODES; i += TOTALT) {
        int d    = g_degi[i];
        int excl = g_scan[i] + g_boff[i / CH];
        g_rowptr[i] = excl;
        g_fill[i]   = excl;
        g_dinv[i]   = (d > 0) ? rsqrtf((float)d) : 0.f;
    }
    if (gtid == 0) g_rowptr[N_NODES] = N_EDGES;
    grid_barrier();

    // ---- P5a: transform U[n] = dinv[n]*(F[n]@W)  (packed f32x2 FMA) ----
    for (int i = tid; i < DFEAT * (UNITS / 4); i += NT)
        Ws[i] = reinterpret_cast<const float4*>(W)[i];
    __syncthreads();

    for (int node = gtid; node < N_NODES; node += TOTALT) {
        unsigned long long acc[32];
#pragma unroll
        for (int j = 0; j < 32; j++) acc[j] = 0ull;
        const float4* Frow = reinterpret_cast<const float4*>(F + (size_t)node * DFEAT);
#pragma unroll 4
        for (int k4 = 0; k4 < 16; k4++) {
            float4 f = Frow[k4];
            float fv[4] = {f.x, f.y, f.z, f.w};
#pragma unroll
            for (int kk = 0; kk < 4; kk++) {
                unsigned long long p2;
                PACK_DUP_F32X2(p2, __float_as_uint(fv[kk]));
                const unsigned long long* wrow =
                    reinterpret_cast<const unsigned long long*>(&Ws[(k4 * 4 + kk) * 16]);
#pragma unroll
                for (int j = 0; j < 32; j++) FMA_F32X2(acc[j], p2, wrow[j]);
            }
        }
        float dv = g_dinv[node];
        float4* Urow = &g_U[(size_t)node * 16];
#pragma unroll
        for (int j = 0; j < 16; j++) {
            float2 lo = *reinterpret_cast<float2*>(&acc[2 * j]);
            float2 hi = *reinterpret_cast<float2*>(&acc[2 * j + 1]);
            Urow[j] = make_float4(lo.x * dv, lo.y * dv, hi.x * dv, hi.y * dv);
        }
    }

    // ---- P5b: CSR fill (same phase; overlaps transform across blocks) ----
    for (int t = gtid; t < E4; t += TOTALT) {
        int r[4], c[4];
        load_edges4(ei, t, 0, r, is64);
        load_edges4(ei, t, N_EDGES, c, is64);
#pragma unroll
        for (int k = 0; k < 4; k++) {
            int pos = atomicAdd(&g_fill[r[k]], 1);
            g_col[pos] = c[k];
        }
    }
}

// ---------------------------------------------------------------------------
// Kernel B: gather + epilogue, full occupancy.
// 8 threads per node; each handles chunks c and c+8 (2 float4 per index).
// ---------------------------------------------------------------------------
__global__ void k_gather(float4* __restrict__ out4,
                         const float* __restrict__ bias) {
    int gid = blockIdx.x * blockDim.x + threadIdx.x;
    int node = gid >> 3;
    int h = gid & 7;
    if (node >= N_NODES) return;

    int c0 = h;
    int c1 = h + 8;
    int start = g_rowptr[node];
    int end   = g_rowptr[node + 1];

    float4 a0 = make_float4(0.f, 0.f, 0.f, 0.f);
    float4 a1 = make_float4(0.f, 0.f, 0.f, 0.f);
    float4 b0 = make_float4(0.f, 0.f, 0.f, 0.f);
    float4 b1 = make_float4(0.f, 0.f, 0.f, 0.f);

    int j = start;
    for (; j + 1 < end; j += 2) {
        int i0 = g_col[j];
        int i1 = g_col[j + 1];
        float4 u00 = g_U[i0 * 16 + c0];
        float4 u01 = g_U[i0 * 16 + c1];
        float4 u10 = g_U[i1 * 16 + c0];
        float4 u11 = g_U[i1 * 16 + c1];
        a0.x += u00.x; a0.y += u00.y; a0.z += u00.z; a0.w += u00.w;
        a1.x += u01.x; a1.y += u01.y; a1.z += u01.z; a1.w += u01.w;
        b0.x += u10.x; b0.y += u10.y; b0.z += u10.z; b0.w += u10.w;
        b1.x += u11.x; b1.y += u11.y; b1.z += u11.z; b1.w += u11.w;
    }
    if (j < end) {
        int i0 = g_col[j];
        float4 u00 = g_U[i0 * 16 + c0];
        float4 u01 = g_U[i0 * 16 + c1];
        a0.x += u00.x; a0.y += u00.y; a0.z += u00.z; a0.w += u00.w;
        a1.x += u01.x; a1.y += u01.y; a1.z += u01.z; a1.w += u01.w;
    }
    a0.x += b0.x; a0.y += b0.y; a0.z += b0.z; a0.w += b0.w;
    a1.x += b1.x; a1.y += b1.y; a1.z += b1.z; a1.w += b1.w;

    float dv = g_dinv[node];
    float4 bb0 = reinterpret_cast<const float4*>(bias)[c0];
    float4 bb1 = reinterpret_cast<const float4*>(bias)[c1];
    float4 v0, v1;
    v0.x = fmaxf(fmaf(dv, a0.x, bb0.x), 0.f);
    v0.y = fmaxf(fmaf(dv, a0.y, bb0.y), 0.f);
    v0.z = fmaxf(fmaf(dv, a0.z, bb0.z), 0.f);
    v0.w = fmaxf(fmaf(dv, a0.w, bb0.w), 0.f);
    v1.x = fmaxf(fmaf(dv, a1.x, bb1.x), 0.f);
    v1.y = fmaxf(fmaf(dv, a1.y, bb1.y), 0.f);
    v1.z = fmaxf(fmaf(dv, a1.z, bb1.z), 0.f);
    v1.w = fmaxf(fmaf(dv, a1.w, bb1.w), 0.f);
    out4[node * 16 + c0] = v0;
    out4[node * 16 + c1] = v1;
}

// ---------------------------------------------------------------------------
extern "C" void kernel_launch(void* const* d_in, const int* in_sizes, int n_in,
                              void* d_out, int out_size) {
    const float* features = (const float*)d_in[0];       // [N, 64]
    const void*  edge_idx = d_in[1];                     // [2, E] int32 or int64
    const float* weight   = (const float*)d_in[2];       // [64, 64]
    const float* bias     = (const float*)d_in[3];       // [64]
    float4*      out4     = (float4*)d_out;              // [N, 64] fp32

    k_setup<<<NBLOCKS, NT>>>(features, edge_idx, weight);
    const int B = 256;
    k_gather<<<(N_NODES * 8 + B - 1) / B, B>>>(out4, bias);
}

// round 8
// speedup vs baseline: 1.1548x; 1.1241x over previous
#include <cuda_runtime.h>
#include <cuda_fp16.h>
#include <cstdint>

#define N_NODES 100000
#define N_EDGES 1250000
#define DFEAT   64
#define UNITS   64

#define E4      (N_EDGES / 4)                          // 312500
#define SCAN_B  1024
#define NB_SCAN ((N_NODES + SCAN_B - 1) / SCAN_B)      // 98

// transform/fill block split
#define TB      160
#define FB      288

// ---- scratch (device globals; allocation-free) ----
__device__ __half2 g_U[(size_t)N_NODES * (UNITS / 2)]; // dinv[n]*(F[n]@W) fp16, 12.8 MB
__device__ int     g_degi[N_NODES];
__device__ float   g_dinv[N_NODES];
__device__ int     g_rowptr[N_NODES + 1];
__device__ int     g_fill[N_NODES];
__device__ int     g_col[N_EDGES];
__device__ int     g_is64;
// decoupled-lookback scan state
__device__ int     g_agg[NB_SCAN];
__device__ int     g_inc[NB_SCAN];
__device__ int     g_flag[NB_SCAN];   // 0=none, 1=aggregate, 2=inclusive

// f32x2 packed FMA helpers (Blackwell FFMA2)
#define FMA_F32X2(acc, a, b) \
    asm("fma.rn.f32x2 %0, %1, %2, %0;" : "+l"(acc) : "l"(a), "l"(b))
#define PACK_DUP_F32X2(out, s) \
    asm("mov.b64 %0, {%1, %1};" : "=l"(out) : "r"(s))

__device__ __forceinline__ void load_edges4(const void* __restrict__ ei,
                                            int t, size_t elem_off, int v[4], int is64) {
    if (is64) {
        const longlong2* p = (const longlong2*)((const long long*)ei + elem_off);
        longlong2 a = p[t * 2];
        longlong2 b = p[t * 2 + 1];
        v[0] = (int)a.x; v[1] = (int)a.y; v[2] = (int)b.x; v[3] = (int)b.y;
    } else {
        int4 a = ((const int4*)((const int*)ei + elem_off))[t];
        v[0] = a.x; v[1] = a.y; v[2] = a.z; v[3] = a.w;
    }
}

// ---------------------------------------------------------------------------
// K1: zero degree counters + scan flags + dtype detect
// ---------------------------------------------------------------------------
__global__ void k_zero_detect(const void* __restrict__ ei) {
    int i = blockIdx.x * blockDim.x + threadIdx.x;
    int stride = gridDim.x * blockDim.x;
    for (int j = i; j < N_NODES; j += stride) g_degi[j] = 0;
    if (i < NB_SCAN) { g_flag[i] = 0; g_agg[i] = 0; g_inc[i] = 0; }

    if (blockIdx.x == 0 && threadIdx.x < 32) {
        const long long* p = (const long long*)ei;
        int bad = 0;
#pragma unroll
        for (int k = 0; k < 8; k++) {
            long long v = p[threadIdx.x * 8 + k];
            bad |= (v < 0 || v >= N_NODES);
        }
        unsigned any = __ballot_sync(0xFFFFFFFFu, bad);
        if (threadIdx.x == 0) g_is64 = (any == 0u) ? 1 : 0;
    }
}

// ---------------------------------------------------------------------------
// K2: degree count (4 edges/thread)
// ---------------------------------------------------------------------------
__global__ void k_degree(const void* __restrict__ ei) {
    int t = blockIdx.x * blockDim.x + threadIdx.x;
    if (t >= E4) return;
    int r[4];
    load_edges4(ei, t, 0, r, g_is64);
#pragma unroll
    for (int k = 0; k < 4; k++) atomicAdd(&g_degi[r[k]], 1);
}

// ---------------------------------------------------------------------------
// K3: single-pass scan (decoupled lookback) + rowptr/fill/dinv finalize
// ---------------------------------------------------------------------------
__global__ void __launch_bounds__(SCAN_B)
k_scan() {
    __shared__ int s[SCAN_B];
    __shared__ int s_prefix;
    int tid = threadIdx.x;
    int bid = blockIdx.x;
    int i = bid * SCAN_B + tid;

    int d = (i < N_NODES) ? g_degi[i] : 0;
    s[tid] = d;
    __syncthreads();
#pragma unroll
    for (int off = 1; off < SCAN_B; off <<= 1) {
        int t = (tid >= off) ? s[tid - off] : 0;
        __syncthreads();
        s[tid] += t;
        __syncthreads();
    }
    int incl = s[tid];
    int block_total = s[SCAN_B - 1];

    if (tid == 0) {
        int prefix = 0;
        if (bid == 0) {
            atomicExch(&g_inc[0], block_total);
            __threadfence();
            atomicExch(&g_flag[0], 2);
        } else {
            atomicExch(&g_agg[bid], block_total);
            __threadfence();
            atomicExch(&g_flag[bid], 1);
            int p = bid - 1;
            while (p >= 0) {
                int f;
                while ((f = atomicAdd(&g_flag[p], 0)) == 0) __nanosleep(32);
                if (f == 2) { prefix += atomicAdd(&g_inc[p], 0); break; }
                prefix += atomicAdd(&g_agg[p], 0);
                p--;
            }
            atomicExch(&g_inc[bid], prefix + block_total);
            __threadfence();
            atomicExch(&g_flag[bid], 2);
        }
        s_prefix = prefix;
    }
    __syncthreads();

    if (i < N_NODES) {
        int excl = s_prefix + incl - d;
        g_rowptr[i] = excl;
        g_fill[i]   = excl;
        g_dinv[i]   = (d > 0) ? rsqrtf((float)d) : 0.f;
    }
    if (i == 0) g_rowptr[N_NODES] = N_EDGES;
}

// ---------------------------------------------------------------------------
// K4: block-split — transform (blocks [0,TB)) || CSR fill (blocks [TB,TB+FB))
// ---------------------------------------------------------------------------
__global__ void __launch_bounds__(256)
k_transfill(const float* __restrict__ F, const float* __restrict__ W,
            const void* __restrict__ ei) {
    const int tid = threadIdx.x;

    if (blockIdx.x < TB) {
        // ---- transform: U[n] = fp16( dinv[n] * (F[n] @ W) ) ----
        __shared__ float4 Ws[DFEAT * (UNITS / 4)];  // 16 KB
        for (int i = tid; i < DFEAT * (UNITS / 4); i += 256)
            Ws[i] = reinterpret_cast<const float4*>(W)[i];
        __syncthreads();

        const int nthr = TB * 256;
        for (int node = blockIdx.x * 256 + tid; node < N_NODES; node += nthr) {
            unsigned long long acc[32];
#pragma unroll
            for (int j = 0; j < 32; j++) acc[j] = 0ull;
            const float4* Frow = reinterpret_cast<const float4*>(F + (size_t)node * DFEAT);
#pragma unroll 4
            for (int k4 = 0; k4 < 16; k4++) {
                float4 f = Frow[k4];
                float fv[4] = {f.x, f.y, f.z, f.w};
#pragma unroll
                for (int kk = 0; kk < 4; kk++) {
                    unsigned long long p2;
                    PACK_DUP_F32X2(p2, __float_as_uint(fv[kk]));
                    const unsigned long long* wrow =
                        reinterpret_cast<const unsigned long long*>(&Ws[(k4 * 4 + kk) * 16]);
#pragma unroll
                    for (int j = 0; j < 32; j++) FMA_F32X2(acc[j], p2, wrow[j]);
                }
            }
            float dv = g_dinv[node];
            __half2* Urow = &g_U[(size_t)node * 32];
#pragma unroll
            for (int j = 0; j < 32; j++) {
                float2 p = *reinterpret_cast<float2*>(&acc[j]);
                Urow[j] = __floats2half2_rn(p.x * dv, p.y * dv);
            }
        }
    } else {
        // ---- CSR fill ----
        const int fb = blockIdx.x - TB;
        const int nthr = FB * 256;
        const int is64 = g_is64;
        for (int t = fb * 256 + tid; t < E4; t += nthr) {
            int r[4], c[4];
            load_edges4(ei, t, 0, r, is64);
            load_edges4(ei, t, N_EDGES, c, is64);
#pragma unroll
            for (int k = 0; k < 4; k++) {
                int pos = atomicAdd(&g_fill[r[k]], 1);
                g_col[pos] = c[k];
            }
        }
    }
}

// ---------------------------------------------------------------------------
// K5: gather + epilogue. 8 threads/node; thread h owns halves [h*8, h*8+8)
//     = one uint4 (16B) of the 128B fp16 row. fp32 accumulation, no atomics.
// ---------------------------------------------------------------------------
__global__ void k_gather(float4* __restrict__ out4,
                         const float* __restrict__ bias) {
    int gid = blockIdx.x * blockDim.x + threadIdx.x;
    int node = gid >> 3;
    int h = gid & 7;
    if (node >= N_NODES) return;

    const uint4* Ub = reinterpret_cast<const uint4*>(g_U);  // 8 uint4 per row
    int start = g_rowptr[node];
    int end   = g_rowptr[node + 1];

    float2 a0 = make_float2(0.f, 0.f), a1 = a0, a2 = a0, a3 = a0;
    float2 b0 = a0, b1 = a0, b2 = a0, b3 = a0;

    int j = start;
    for (; j + 1 < end; j += 2) {
        int i0 = g_col[j];
        int i1 = g_col[j + 1];
        uint4 u = Ub[i0 * 8 + h];
        uint4 v = Ub[i1 * 8 + h];
        float2 f;
        f = __half22float2(*(__half2*)&u.x); a0.x += f.x; a0.y += f.y;
        f = __half22float2(*(__half2*)&u.y); a1.x += f.x; a1.y += f.y;
        f = __half22float2(*(__half2*)&u.z); a2.x += f.x; a2.y += f.y;
        f = __half22float2(*(__half2*)&u.w); a3.x += f.x; a3.y += f.y;
        f = __half22float2(*(__half2*)&v.x); b0.x += f.x; b0.y += f.y;
        f = __half22float2(*(__half2*)&v.y); b1.x += f.x; b1.y += f.y;
        f = __half22float2(*(__half2*)&v.z); b2.x += f.x; b2.y += f.y;
        f = __half22float2(*(__half2*)&v.w); b3.x += f.x; b3.y += f.y;
    }
    if (j < end) {
        uint4 u = Ub[g_col[j] * 8 + h];
        float2 f;
        f = __half22float2(*(__half2*)&u.x); a0.x += f.x; a0.y += f.y;
        f = __half22float2(*(__half2*)&u.y); a1.x += f.x; a1.y += f.y;
        f = __half22float2(*(__half2*)&u.z); a2.x += f.x; a2.y += f.y;
        f = __half22float2(*(__half2*)&u.w); a3.x += f.x; a3.y += f.y;
    }
    a0.x += b0.x; a0.y += b0.y;  a1.x += b1.x; a1.y += b1.y;
    a2.x += b2.x; a2.y += b2.y;  a3.x += b3.x; a3.y += b3.y;

    float dv = g_dinv[node];
    float4 bb0 = reinterpret_cast<const float4*>(bias)[h * 2];
    float4 bb1 = reinterpret_cast<const float4*>(bias)[h * 2 + 1];
    float4 v0, v1;
    v0.x = fmaxf(fmaf(dv, a0.x, bb0.x), 0.f);
    v0.y = fmaxf(fmaf(dv, a0.y, bb0.y), 0.f);
    v0.z = fmaxf(fmaf(dv, a1.x, bb0.z), 0.f);
    v0.w = fmaxf(fmaf(dv, a1.y, bb0.w), 0.f);
    v1.x = fmaxf(fmaf(dv, a2.x, bb1.x), 0.f);
    v1.y = fmaxf(fmaf(dv, a2.y, bb1.y), 0.f);
    v1.z = fmaxf(fmaf(dv, a3.x, bb1.z), 0.f);
    v1.w = fmaxf(fmaf(dv, a3.y, bb1.w), 0.f);
    out4[node * 16 + h * 2]     = v0;
    out4[node * 16 + h * 2 + 1] = v1;
}

// ---------------------------------------------------------------------------
extern "C" void kernel_launch(void* const* d_in, const int* in_sizes, int n_in,
                              void* d_out, int out_size) {
    const float* features = (const float*)d_in[0];       // [N, 64]
    const void*  edge_idx = d_in[1];                     // [2, E] int32 or int64
    const float* weight   = (const float*)d_in[2];       // [64, 64]
    const float* bias     = (const float*)d_in[3];       // [64]
    float4*      out4     = (float4*)d_out;              // [N, 64] fp32

    const int B = 256;

    k_zero_detect<<<512, B>>>(edge_idx);
    k_degree<<<(E4 + B - 1) / B, B>>>(edge_idx);
    k_scan<<<NB_SCAN, SCAN_B>>>();
    k_transfill<<<TB + FB, B>>>(features, weight, edge_idx);
    k_gather<<<(N_NODES * 8 + B - 1) / B, B>>>(out4, bias);
}